// round 1
// baseline (speedup 1.0000x reference)
#include <cuda_runtime.h>
#include <cuda_bf16.h>
#include <math.h>

// Problem constants (fixed shapes from setup_inputs)
#define BATCH 4
#define SEQ   2048
#define DMODEL 1024
#define NHEADS 16
#define FDIM  16
#define HDIM  64
#define NTOK  (BATCH*SEQ)          // 8192
#define QKDIM (NHEADS*FDIM)        // 256
#define VDIM  (NHEADS*HDIM)        // 1024
#define FEAT  273                  // 1 + 16 + 256
#define KV_ELEMS (BATCH*NHEADS*HDIM*FEAT)   // 1,118,208
#define OUT_ELEMS (NTOK*DMODEL)             // 8,388,608

// Scratch (device globals; no runtime allocation)
__device__ float g_Q[NTOK*QKDIM];           // [tok, h*16+i]
__device__ float g_K[NTOK*QKDIM];
__device__ float g_V[NTOK*VDIM];            // [tok, h*64+f]
__device__ float g_Y[NTOK*VDIM];            // normed y, [tok, h*64+f]
__device__ float g_KVp[64*8*HDIM*FEAT];     // kv_state partials: [bh, chunk, f, d]

// ---------------------------------------------------------------------------
// SGEMM: C[M,N] = A[M,K] @ B[N,K]^T   (A,B row-major; all dims multiples of 128/8)
// 128x128 block tile, 8x8 microtile, BK=8, 256 threads.
// ---------------------------------------------------------------------------
__global__ __launch_bounds__(256, 2)
void sgemm_nt(const float* __restrict__ A, const float* __restrict__ B,
              float* __restrict__ C, int M, int N, int K) {
    __shared__ float As[8][128];
    __shared__ float Bs[8][128];
    const int tid = threadIdx.x;
    const int tx = tid & 15, ty = tid >> 4;
    const int bm = blockIdx.x << 7, bn = blockIdx.y << 7;
    const int lr = tid >> 1;              // 0..127
    const int lc = (tid & 1) << 2;        // 0 or 4
    const float* Ap = A + (size_t)(bm + lr) * K + lc;
    const float* Bp = B + (size_t)(bn + lr) * K + lc;

    float acc[8][8];
#pragma unroll
    for (int i = 0; i < 8; i++)
#pragma unroll
        for (int j = 0; j < 8; j++) acc[i][j] = 0.f;

    for (int k0 = 0; k0 < K; k0 += 8) {
        float4 av = *(const float4*)(Ap + k0);
        float4 bv = *(const float4*)(Bp + k0);
        __syncthreads();
        As[lc + 0][lr] = av.x; As[lc + 1][lr] = av.y;
        As[lc + 2][lr] = av.z; As[lc + 3][lr] = av.w;
        Bs[lc + 0][lr] = bv.x; Bs[lc + 1][lr] = bv.y;
        Bs[lc + 2][lr] = bv.z; Bs[lc + 3][lr] = bv.w;
        __syncthreads();
#pragma unroll
        for (int kk = 0; kk < 8; kk++) {
            float a[8], b[8];
            *(float4*)&a[0] = *(const float4*)&As[kk][ty * 8];
            *(float4*)&a[4] = *(const float4*)&As[kk][ty * 8 + 4];
            *(float4*)&b[0] = *(const float4*)&Bs[kk][tx * 8];
            *(float4*)&b[4] = *(const float4*)&Bs[kk][tx * 8 + 4];
#pragma unroll
            for (int i = 0; i < 8; i++)
#pragma unroll
                for (int j = 0; j < 8; j++)
                    acc[i][j] = fmaf(a[i], b[j], acc[i][j]);
        }
    }
#pragma unroll
    for (int i = 0; i < 8; i++) {
        size_t off = (size_t)(bm + ty * 8 + i) * N + bn + tx * 8;
        *(float4*)&C[off]     = make_float4(acc[i][0], acc[i][1], acc[i][2], acc[i][3]);
        *(float4*)&C[off + 4] = make_float4(acc[i][4], acc[i][5], acc[i][6], acc[i][7]);
    }
}

// ---------------------------------------------------------------------------
// Causal attention with the Taylor-kernel scalar trick:
//   A(n,m) = 1 + s/4 + s^2/32,  s = q_n · k_m  (16-dim)
// Block: (q-tile of 128 rows) x (b,h). 256 threads: 2 threads per q-row,
// each owning 32 of the 64 v columns. Fused RMSNorm + g_weight.
// ---------------------------------------------------------------------------
__global__ __launch_bounds__(256, 4)
void attn_kernel(const float* __restrict__ Q, const float* __restrict__ Km,
                 const float* __restrict__ V, const float* __restrict__ g,
                 float* __restrict__ Y) {
    __shared__ float Ks[128][16];
    __shared__ float Vs[128][64];
    const int qt = (int)gridDim.x - 1 - (int)blockIdx.x;   // long blocks first
    const int bh = blockIdx.y;
    const int b = bh >> 4, h = bh & 15;
    const int tid = threadIdx.x;
    const int row = tid >> 1;
    const int ch = (tid & 1) * 32;
    const int qrow = qt * 128 + row;
    const int tokb = b * SEQ;

    float q[16];
    const float* qp = Q + (size_t)(tokb + qrow) * QKDIM + h * FDIM;
#pragma unroll
    for (int i = 0; i < 16; i++) q[i] = qp[i];

    float acc[32];
#pragma unroll
    for (int c = 0; c < 32; c++) acc[c] = 0.f;

    for (int kt = 0; kt <= qt; kt++) {
        __syncthreads();
        // stage K tile (128x16) and V tile (128x64)
        for (int t = tid; t < 512; t += 256) {
            int r = t >> 2, c4 = (t & 3) << 2;
            *(float4*)&Ks[r][c4] =
                *(const float4*)&Km[(size_t)(tokb + kt * 128 + r) * QKDIM + h * FDIM + c4];
        }
        for (int t = tid; t < 2048; t += 256) {
            int r = t >> 4, c4 = (t & 15) << 2;
            *(float4*)&Vs[r][c4] =
                *(const float4*)&V[(size_t)(tokb + kt * 128 + r) * VDIM + h * HDIM + c4];
        }
        __syncthreads();

        const int jend = (kt == qt) ? (row + 1) : 128;
        for (int j = 0; j < jend; j++) {
            float4 k0 = *(const float4*)&Ks[j][0];
            float4 k1 = *(const float4*)&Ks[j][4];
            float4 k2 = *(const float4*)&Ks[j][8];
            float4 k3 = *(const float4*)&Ks[j][12];
            float s = q[0] * k0.x;
            s = fmaf(q[1], k0.y, s);  s = fmaf(q[2], k0.z, s);  s = fmaf(q[3], k0.w, s);
            s = fmaf(q[4], k1.x, s);  s = fmaf(q[5], k1.y, s);  s = fmaf(q[6], k1.z, s);
            s = fmaf(q[7], k1.w, s);  s = fmaf(q[8], k2.x, s);  s = fmaf(q[9], k2.y, s);
            s = fmaf(q[10], k2.z, s); s = fmaf(q[11], k2.w, s); s = fmaf(q[12], k3.x, s);
            s = fmaf(q[13], k3.y, s); s = fmaf(q[14], k3.z, s); s = fmaf(q[15], k3.w, s);
            // A = 1 + s/4 + s^2/32  (== qf·kf of the Taylor feature map)
            float a = fmaf(s, 0.25f, 1.0f);
            a = fmaf(s * s, 0.03125f, a);
            const float4* vr = (const float4*)&Vs[j][ch];
#pragma unroll
            for (int c4 = 0; c4 < 8; c4++) {
                float4 v = vr[c4];
                acc[c4 * 4 + 0] = fmaf(a, v.x, acc[c4 * 4 + 0]);
                acc[c4 * 4 + 1] = fmaf(a, v.y, acc[c4 * 4 + 1]);
                acc[c4 * 4 + 2] = fmaf(a, v.z, acc[c4 * 4 + 2]);
                acc[c4 * 4 + 3] = fmaf(a, v.w, acc[c4 * 4 + 3]);
            }
        }
    }

    // RMSNorm over the 64 head dims (split across thread pair lane^1)
    float ss = 0.f;
#pragma unroll
    for (int c = 0; c < 32; c++) ss = fmaf(acc[c], acc[c], ss);
    ss += __shfl_xor_sync(0xffffffffu, ss, 1);
    const float rms = rsqrtf(ss * (1.0f / 64.0f) + 1e-5f);

    float* yp = Y + (size_t)(tokb + qrow) * VDIM + h * HDIM + ch;
#pragma unroll
    for (int c4 = 0; c4 < 8; c4++) {
        float4 o;
        o.x = acc[c4 * 4 + 0] * rms * g[ch + c4 * 4 + 0];
        o.y = acc[c4 * 4 + 1] * rms * g[ch + c4 * 4 + 1];
        o.z = acc[c4 * 4 + 2] * rms * g[ch + c4 * 4 + 2];
        o.w = acc[c4 * 4 + 3] * rms * g[ch + c4 * 4 + 3];
        *(float4*)&yp[c4 * 4] = o;
    }
}

// ---------------------------------------------------------------------------
// kv_state partials: kv[b,h,f,d] = sum_n kf[n,d] * v[n,f]
//   d=0: sum v ; d=1+i: (1/2) sum k_i v ; d=17+16i+j: (1/(4*sqrt2)) sum k_i k_j v
// grid (chunk=8, bh=64); each block covers 256 tokens.
// thread = (i in 0..15) x (fgrp in 0..15, 4 f's each)
// ---------------------------------------------------------------------------
__global__ __launch_bounds__(256, 2)
void kv_partial(const float* __restrict__ Km, const float* __restrict__ V,
                float* __restrict__ P) {
    __shared__ float ks[32][16];
    __shared__ float vs[32][64];
    const int ck = blockIdx.x;           // 0..7
    const int bh = blockIdx.y;           // 0..63
    const int b = bh >> 4, h = bh & 15;
    const int tid = threadIdx.x;
    const int i = tid >> 4;
    const int f0 = (tid & 15) << 2;
    const int n0 = ck * 256;
    const int tokb = b * SEQ;

    float m2[16][4];
#pragma unroll
    for (int j = 0; j < 16; j++)
#pragma unroll
        for (int ff = 0; ff < 4; ff++) m2[j][ff] = 0.f;
    float m1[4] = {0.f, 0.f, 0.f, 0.f};
    float s0[4] = {0.f, 0.f, 0.f, 0.f};

    for (int nb = 0; nb < 256; nb += 32) {
        __syncthreads();
        for (int t = tid; t < 128; t += 256) {
            int r = t >> 2, c4 = (t & 3) << 2;
            *(float4*)&ks[r][c4] =
                *(const float4*)&Km[(size_t)(tokb + n0 + nb + r) * QKDIM + h * FDIM + c4];
        }
        for (int t = tid; t < 512; t += 256) {
            int r = t >> 4, c4 = (t & 15) << 2;
            *(float4*)&vs[r][c4] =
                *(const float4*)&V[(size_t)(tokb + n0 + nb + r) * VDIM + h * HDIM + c4];
        }
        __syncthreads();
#pragma unroll 4
        for (int r = 0; r < 32; r++) {
            const float ki = ks[r][i];
            const float4 v4 = *(const float4*)&vs[r][f0];
            m1[0] = fmaf(ki, v4.x, m1[0]);
            m1[1] = fmaf(ki, v4.y, m1[1]);
            m1[2] = fmaf(ki, v4.z, m1[2]);
            m1[3] = fmaf(ki, v4.w, m1[3]);
            if (i == 0) {
                s0[0] += v4.x; s0[1] += v4.y; s0[2] += v4.z; s0[3] += v4.w;
            }
#pragma unroll
            for (int j = 0; j < 16; j++) {
                const float kk = ki * ks[r][j];
                m2[j][0] = fmaf(kk, v4.x, m2[j][0]);
                m2[j][1] = fmaf(kk, v4.y, m2[j][1]);
                m2[j][2] = fmaf(kk, v4.z, m2[j][2]);
                m2[j][3] = fmaf(kk, v4.w, m2[j][3]);
            }
        }
    }

    float* p = P + ((size_t)bh * 8 + ck) * (HDIM * FEAT);
    const float c2 = 0.17677669529663687f;   // 1/(4*sqrt(2))
    const float c1 = 0.5f;                   // 1/RRD
#pragma unroll
    for (int ff = 0; ff < 4; ff++) {
        float* pf = p + (size_t)(f0 + ff) * FEAT;
#pragma unroll
        for (int j = 0; j < 16; j++)
            pf[17 + i * 16 + j] = m2[j][ff] * c2;
        pf[1 + i] = m1[ff] * c1;
        if (i == 0) pf[0] = s0[ff];
    }
}

__global__ void kv_reduce(const float* __restrict__ P, float* __restrict__ out) {
    const int idx = blockIdx.x * 256 + threadIdx.x;   // 0..KV_ELEMS-1
    const int bh = idx / (HDIM * FEAT);
    const int r = idx - bh * (HDIM * FEAT);
    float s = 0.f;
#pragma unroll
    for (int c = 0; c < 8; c++)
        s += P[((size_t)bh * 8 + c) * (HDIM * FEAT) + r];
    out[idx] = s;
}

// ---------------------------------------------------------------------------
extern "C" void kernel_launch(void* const* d_in, const int* in_sizes, int n_in,
                              void* d_out, int out_size) {
    const float* X  = (const float*)d_in[0];   // [4,2048,1024]
    const float* Wq = (const float*)d_in[1];   // [256,1024]
    const float* Wk = (const float*)d_in[2];   // [256,1024]
    const float* Wv = (const float*)d_in[3];   // [1024,1024]
    const float* Wo = (const float*)d_in[4];   // [1024,1024]
    const float* g  = (const float*)d_in[5];   // [64]
    float* out = (float*)d_out;

    float *Qb, *Kb, *Vb, *Yb, *Pb;
    cudaGetSymbolAddress((void**)&Qb, g_Q);
    cudaGetSymbolAddress((void**)&Kb, g_K);
    cudaGetSymbolAddress((void**)&Vb, g_V);
    cudaGetSymbolAddress((void**)&Yb, g_Y);
    cudaGetSymbolAddress((void**)&Pb, g_KVp);

    // Projections
    sgemm_nt<<<dim3(NTOK / 128, QKDIM / 128), 256>>>(X, Wq, Qb, NTOK, QKDIM, DMODEL);
    sgemm_nt<<<dim3(NTOK / 128, QKDIM / 128), 256>>>(X, Wk, Kb, NTOK, QKDIM, DMODEL);
    sgemm_nt<<<dim3(NTOK / 128, VDIM / 128),  256>>>(X, Wv, Vb, NTOK, VDIM,  DMODEL);

    // Causal attention + RMSNorm + gate
    attn_kernel<<<dim3(SEQ / 128, BATCH * NHEADS), 256>>>(Qb, Kb, Vb, g, Yb);

    // Output projection -> first output
    sgemm_nt<<<dim3(NTOK / 128, DMODEL / 128), 256>>>(Yb, Wo, out, NTOK, DMODEL, DMODEL);

    // kv_state -> second output (if present in the flattened output buffer)
    if (out_size >= OUT_ELEMS + KV_ELEMS) {
        kv_partial<<<dim3(8, BATCH * NHEADS), 256>>>(Kb, Vb, Pb);
        kv_reduce<<<KV_ELEMS / 256, 256>>>(Pb, out + OUT_ELEMS);
    }
}

// round 2
// speedup vs baseline: 1.7658x; 1.7658x over previous
#include <cuda_runtime.h>
#include <cuda_bf16.h>
#include <math.h>

// Problem constants (fixed shapes from setup_inputs)
#define BATCH 4
#define SEQ   2048
#define DMODEL 1024
#define NHEADS 16
#define FDIM  16
#define HDIM  64
#define NTOK  (BATCH*SEQ)          // 8192
#define QKDIM (NHEADS*FDIM)        // 256
#define VDIM  (NHEADS*HDIM)        // 1024
#define FEAT  273                  // 1 + 16 + 256
#define NCHUNK 16                  // 2048 / 128
#define CHUNK 128
#define KV_ELEMS (BATCH*NHEADS*HDIM*FEAT)   // 1,118,208
#define OUT_ELEMS (NTOK*DMODEL)             // 8,388,608
#define SDF (FEAT*HDIM)            // 17472

// Scratch (device globals; no runtime allocation)
__device__ float g_Q[NTOK*QKDIM];            // [tok, h*16+i]
__device__ float g_K[NTOK*QKDIM];
__device__ float g_V[NTOK*VDIM];             // [tok, h*64+f]
__device__ float g_Y[NTOK*VDIM];             // normed y, [tok, h*64+f]
__device__ float g_DS[64*NCHUNK*SDF];        // chunk states: [bh, chunk, d(273), f(64)]
                                             // after scan: exclusive prefix (S_prev)

// ---------------------------------------------------------------------------
// SGEMM: C[M,N] = A[M,K] @ B[N,K]^T  (unchanged from round 1)
// ---------------------------------------------------------------------------
__global__ __launch_bounds__(256, 2)
void sgemm_nt(const float* __restrict__ A, const float* __restrict__ B,
              float* __restrict__ C, int M, int N, int K) {
    __shared__ float As[8][128];
    __shared__ float Bs[8][128];
    const int tid = threadIdx.x;
    const int tx = tid & 15, ty = tid >> 4;
    const int bm = blockIdx.x << 7, bn = blockIdx.y << 7;
    const int lr = tid >> 1;
    const int lc = (tid & 1) << 2;
    const float* Ap = A + (size_t)(bm + lr) * K + lc;
    const float* Bp = B + (size_t)(bn + lr) * K + lc;

    float acc[8][8];
#pragma unroll
    for (int i = 0; i < 8; i++)
#pragma unroll
        for (int j = 0; j < 8; j++) acc[i][j] = 0.f;

    for (int k0 = 0; k0 < K; k0 += 8) {
        float4 av = *(const float4*)(Ap + k0);
        float4 bv = *(const float4*)(Bp + k0);
        __syncthreads();
        As[lc + 0][lr] = av.x; As[lc + 1][lr] = av.y;
        As[lc + 2][lr] = av.z; As[lc + 3][lr] = av.w;
        Bs[lc + 0][lr] = bv.x; Bs[lc + 1][lr] = bv.y;
        Bs[lc + 2][lr] = bv.z; Bs[lc + 3][lr] = bv.w;
        __syncthreads();
#pragma unroll
        for (int kk = 0; kk < 8; kk++) {
            float a[8], b[8];
            *(float4*)&a[0] = *(const float4*)&As[kk][ty * 8];
            *(float4*)&a[4] = *(const float4*)&As[kk][ty * 8 + 4];
            *(float4*)&b[0] = *(const float4*)&Bs[kk][tx * 8];
            *(float4*)&b[4] = *(const float4*)&Bs[kk][tx * 8 + 4];
#pragma unroll
            for (int i = 0; i < 8; i++)
#pragma unroll
                for (int j = 0; j < 8; j++)
                    acc[i][j] = fmaf(a[i], b[j], acc[i][j]);
        }
    }
#pragma unroll
    for (int i = 0; i < 8; i++) {
        size_t off = (size_t)(bm + ty * 8 + i) * N + bn + tx * 8;
        *(float4*)&C[off]     = make_float4(acc[i][0], acc[i][1], acc[i][2], acc[i][3]);
        *(float4*)&C[off + 4] = make_float4(acc[i][4], acc[i][5], acc[i][6], acc[i][7]);
    }
}

// ---------------------------------------------------------------------------
// Kernel A: per-chunk state increment  DS[bh,ck,d,f] = sum_{n in chunk} kf[n,d] v[n,f]
// (kf scaled: [1, k/2, k_i k_j/(4*sqrt2)]). grid (16 chunks, 64 bh), 256 thr.
// thread = (i 0..15) x (f-group of 4)
// ---------------------------------------------------------------------------
__global__ __launch_bounds__(256, 2)
void state_kernel(const float* __restrict__ Km, const float* __restrict__ V,
                  float* __restrict__ DS) {
    __shared__ float ks[32][16];
    __shared__ float vs[32][64];
    const int ck = blockIdx.x;
    const int bh = blockIdx.y;
    const int b = bh >> 4, h = bh & 15;
    const int tid = threadIdx.x;
    const int i = tid >> 4;
    const int f0 = (tid & 15) << 2;
    const int tokb = b * SEQ + ck * CHUNK;

    float m2[16][4];
#pragma unroll
    for (int j = 0; j < 16; j++)
#pragma unroll
        for (int ff = 0; ff < 4; ff++) m2[j][ff] = 0.f;
    float m1[4] = {0.f, 0.f, 0.f, 0.f};
    float s0[4] = {0.f, 0.f, 0.f, 0.f};

    for (int nb = 0; nb < CHUNK; nb += 32) {
        __syncthreads();
        for (int t = tid; t < 128; t += 256) {
            int r = t >> 2, c4 = (t & 3) << 2;
            *(float4*)&ks[r][c4] =
                *(const float4*)&Km[(size_t)(tokb + nb + r) * QKDIM + h * FDIM + c4];
        }
        for (int t = tid; t < 512; t += 256) {
            int r = t >> 4, c4 = (t & 15) << 2;
            *(float4*)&vs[r][c4] =
                *(const float4*)&V[(size_t)(tokb + nb + r) * VDIM + h * HDIM + c4];
        }
        __syncthreads();
#pragma unroll 4
        for (int r = 0; r < 32; r++) {
            const float ki = ks[r][i];
            const float4 v4 = *(const float4*)&vs[r][f0];
            m1[0] = fmaf(ki, v4.x, m1[0]);
            m1[1] = fmaf(ki, v4.y, m1[1]);
            m1[2] = fmaf(ki, v4.z, m1[2]);
            m1[3] = fmaf(ki, v4.w, m1[3]);
            if (i == 0) {
                s0[0] += v4.x; s0[1] += v4.y; s0[2] += v4.z; s0[3] += v4.w;
            }
#pragma unroll
            for (int j = 0; j < 16; j++) {
                const float kk = ki * ks[r][j];
                m2[j][0] = fmaf(kk, v4.x, m2[j][0]);
                m2[j][1] = fmaf(kk, v4.y, m2[j][1]);
                m2[j][2] = fmaf(kk, v4.z, m2[j][2]);
                m2[j][3] = fmaf(kk, v4.w, m2[j][3]);
            }
        }
    }

    float* base = DS + (size_t)(bh * NCHUNK + ck) * SDF;
    const float c2 = 0.17677669529663687f;   // 1/(4*sqrt(2))
#pragma unroll
    for (int ff = 0; ff < 4; ff++) {
        const int f = f0 + ff;
#pragma unroll
        for (int j = 0; j < 16; j++)
            base[(17 + i * 16 + j) * HDIM + f] = m2[j][ff] * c2;
        base[(1 + i) * HDIM + f] = m1[ff] * 0.5f;
        if (i == 0) base[f] = s0[ff];
    }
}

// ---------------------------------------------------------------------------
// Kernel B: in-place exclusive scan over the 16 chunk states per bh.
// After this, DS[bh,ck] = sum of states of chunks < ck. Inclusive total ->
// kv_state output (transposed to [bh, f, d]).
// ---------------------------------------------------------------------------
__global__ void scan_kernel(float* __restrict__ DS, float* __restrict__ kv_out) {
    const int bh = blockIdx.y;
    const int e = blockIdx.x * 256 + threadIdx.x;
    if (e >= SDF) return;
    size_t base = (size_t)bh * NCHUNK * SDF + e;
    float run = 0.f;
#pragma unroll
    for (int c = 0; c < NCHUNK; c++) {
        float v = DS[base + (size_t)c * SDF];
        DS[base + (size_t)c * SDF] = run;
        run += v;
    }
    if (kv_out) {
        const int d = e >> 6, f = e & 63;
        kv_out[(size_t)bh * (HDIM * FEAT) + f * FEAT + d] = run;
    }
}

// ---------------------------------------------------------------------------
// Kernel C: y = qf . S_prev  +  intra-chunk causal (scalar Taylor trick),
// fused RMSNorm + g. grid (16 chunks, 64 bh), 256 threads.
// thread = (fg 0..7: 8 f's) x (tg 0..31: 4 tokens)
// ---------------------------------------------------------------------------
__global__ __launch_bounds__(256, 2)
void attn_out_kernel(const float* __restrict__ Q, const float* __restrict__ Km,
                     const float* __restrict__ V, const float* __restrict__ Sprev,
                     const float* __restrict__ g, float* __restrict__ Y) {
    __shared__ float Qs[128][16];   // q * sqrt(c2)
    __shared__ float Kc[128][16];   // raw k
    __shared__ float Vc[128][64];
    __shared__ float Ss[17][64];
    __shared__ float gs[64];
    const int ck = blockIdx.x;
    const int bh = blockIdx.y;
    const int b = bh >> 4, h = bh & 15;
    const int tid = threadIdx.x;
    const int fg = tid & 7, tg = tid >> 3;
    const int f0 = fg * 8;
    const int t0 = tg * 4;
    const int tok0 = b * SEQ + ck * CHUNK;
    const float SC  = 0.4204482076268573f;    // sqrt(1/(4*sqrt2))
    const float LIN = 1.1892071150027210f;    // (1/2)/SC
    const float DOT = 2.3784142300054421f;    // 1/SC

    // stage Q (scaled), K, V, g, and first S segment (rows 0..16)
    for (int t = tid; t < 512; t += 256) {
        int r = t >> 2, c4 = (t & 3) << 2;
        float4 qv = *(const float4*)&Q[(size_t)(tok0 + r) * QKDIM + h * FDIM + c4];
        Qs[r][c4 + 0] = qv.x * SC; Qs[r][c4 + 1] = qv.y * SC;
        Qs[r][c4 + 2] = qv.z * SC; Qs[r][c4 + 3] = qv.w * SC;
        *(float4*)&Kc[r][c4] =
            *(const float4*)&Km[(size_t)(tok0 + r) * QKDIM + h * FDIM + c4];
    }
    for (int t = tid; t < 2048; t += 256) {
        int r = t >> 4, c4 = (t & 15) << 2;
        *(float4*)&Vc[r][c4] =
            *(const float4*)&V[(size_t)(tok0 + r) * VDIM + h * HDIM + c4];
    }
    if (tid < 64) gs[tid] = g[tid];
    const float* Sp = Sprev + (size_t)(bh * NCHUNK + ck) * SDF;
    for (int t = tid; t < 272; t += 256) {
        int r = t >> 4, c4 = (t & 15) << 2;
        *(float4*)&Ss[r][c4] = *(const float4*)&Sp[r * HDIM + c4];
    }
    __syncthreads();

    float acc[4][8];

    // ----- inter-chunk: const + linear features (S rows 0..16) -----
    {
        float sv[8];
        *(float4*)&sv[0] = *(const float4*)&Ss[0][f0];
        *(float4*)&sv[4] = *(const float4*)&Ss[0][f0 + 4];
#pragma unroll
        for (int t = 0; t < 4; t++)
#pragma unroll
            for (int f = 0; f < 8; f++) acc[t][f] = sv[f];   // qf const term = 1
#pragma unroll
        for (int j = 0; j < 16; j++) {
            *(float4*)&sv[0] = *(const float4*)&Ss[1 + j][f0];
            *(float4*)&sv[4] = *(const float4*)&Ss[1 + j][f0 + 4];
#pragma unroll
            for (int t = 0; t < 4; t++) {
                const float m = Qs[t0 + t][j] * LIN;
#pragma unroll
                for (int f = 0; f < 8; f++) acc[t][f] = fmaf(m, sv[f], acc[t][f]);
            }
        }
    }

    // ----- inter-chunk: quadratic features (16 segments of 16 rows) -----
    for (int i = 0; i < 16; i++) {
        __syncthreads();
        {
            int r = tid >> 4, c4 = (tid & 15) << 2;
            *(float4*)&Ss[r][c4] =
                *(const float4*)&Sp[(17 + i * 16 + r) * HDIM + c4];
        }
        __syncthreads();
        float qi[4];
#pragma unroll
        for (int t = 0; t < 4; t++) qi[t] = Qs[t0 + t][i];
#pragma unroll
        for (int j = 0; j < 16; j++) {
            float sv[8];
            *(float4*)&sv[0] = *(const float4*)&Ss[j][f0];
            *(float4*)&sv[4] = *(const float4*)&Ss[j][f0 + 4];
#pragma unroll
            for (int t = 0; t < 4; t++) {
                const float m = qi[t] * Qs[t0 + t][j];
#pragma unroll
                for (int f = 0; f < 8; f++) acc[t][f] = fmaf(m, sv[f], acc[t][f]);
            }
        }
    }

    // ----- intra-chunk causal: A = 1 + s/4 + s^2/32, s = q.k -----
    float qr[4][16];
#pragma unroll
    for (int t = 0; t < 4; t++)
#pragma unroll
        for (int i = 0; i < 16; i++) qr[t][i] = Qs[t0 + t][i];

    const int mEnd = ((tid >> 5) + 1) * 16;   // warp w covers tokens 16w..16w+15
    for (int m = 0; m < mEnd; m++) {
        float s[4] = {0.f, 0.f, 0.f, 0.f};
#pragma unroll
        for (int i = 0; i < 16; i++) {
            const float ki = Kc[m][i];
            s[0] = fmaf(qr[0][i], ki, s[0]);
            s[1] = fmaf(qr[1][i], ki, s[1]);
            s[2] = fmaf(qr[2][i], ki, s[2]);
            s[3] = fmaf(qr[3][i], ki, s[3]);
        }
        float a[4];
#pragma unroll
        for (int t = 0; t < 4; t++) {
            const float sd = s[t] * DOT;
            float av = fmaf(sd, 0.25f, 1.0f);
            av = fmaf(sd * sd, 0.03125f, av);
            a[t] = (m <= t0 + t) ? av : 0.f;
        }
        float v[8];
        *(float4*)&v[0] = *(const float4*)&Vc[m][f0];
        *(float4*)&v[4] = *(const float4*)&Vc[m][f0 + 4];
#pragma unroll
        for (int t = 0; t < 4; t++)
#pragma unroll
            for (int f = 0; f < 8; f++)
                acc[t][f] = fmaf(a[t], v[f], acc[t][f]);
    }

    // ----- RMSNorm over head dim (reduce across 8 fg lanes) + gate + store -----
#pragma unroll
    for (int t = 0; t < 4; t++) {
        float ss = 0.f;
#pragma unroll
        for (int f = 0; f < 8; f++) ss = fmaf(acc[t][f], acc[t][f], ss);
        ss += __shfl_xor_sync(0xffffffffu, ss, 1);
        ss += __shfl_xor_sync(0xffffffffu, ss, 2);
        ss += __shfl_xor_sync(0xffffffffu, ss, 4);
        const float rms = rsqrtf(ss * (1.0f / 64.0f) + 1e-5f);
        float* yp = Y + (size_t)(tok0 + t0 + t) * VDIM + h * HDIM + f0;
        float4 o0, o1;
        o0.x = acc[t][0] * rms * gs[f0 + 0];
        o0.y = acc[t][1] * rms * gs[f0 + 1];
        o0.z = acc[t][2] * rms * gs[f0 + 2];
        o0.w = acc[t][3] * rms * gs[f0 + 3];
        o1.x = acc[t][4] * rms * gs[f0 + 4];
        o1.y = acc[t][5] * rms * gs[f0 + 5];
        o1.z = acc[t][6] * rms * gs[f0 + 6];
        o1.w = acc[t][7] * rms * gs[f0 + 7];
        *(float4*)&yp[0] = o0;
        *(float4*)&yp[4] = o1;
    }
}

// ---------------------------------------------------------------------------
extern "C" void kernel_launch(void* const* d_in, const int* in_sizes, int n_in,
                              void* d_out, int out_size) {
    const float* X  = (const float*)d_in[0];   // [4,2048,1024]
    const float* Wq = (const float*)d_in[1];   // [256,1024]
    const float* Wk = (const float*)d_in[2];   // [256,1024]
    const float* Wv = (const float*)d_in[3];   // [1024,1024]
    const float* Wo = (const float*)d_in[4];   // [1024,1024]
    const float* g  = (const float*)d_in[5];   // [64]
    float* out = (float*)d_out;

    float *Qb, *Kb, *Vb, *Yb, *Sb;
    cudaGetSymbolAddress((void**)&Qb, g_Q);
    cudaGetSymbolAddress((void**)&Kb, g_K);
    cudaGetSymbolAddress((void**)&Vb, g_V);
    cudaGetSymbolAddress((void**)&Yb, g_Y);
    cudaGetSymbolAddress((void**)&Sb, g_DS);

    // Projections
    sgemm_nt<<<dim3(NTOK / 128, QKDIM / 128), 256>>>(X, Wq, Qb, NTOK, QKDIM, DMODEL);
    sgemm_nt<<<dim3(NTOK / 128, QKDIM / 128), 256>>>(X, Wk, Kb, NTOK, QKDIM, DMODEL);
    sgemm_nt<<<dim3(NTOK / 128, VDIM / 128),  256>>>(X, Wv, Vb, NTOK, VDIM,  DMODEL);

    // Chunked linear attention
    float* kv_out = (out_size >= OUT_ELEMS + KV_ELEMS) ? (out + OUT_ELEMS) : nullptr;
    state_kernel<<<dim3(NCHUNK, BATCH * NHEADS), 256>>>(Kb, Vb, Sb);
    scan_kernel<<<dim3((SDF + 255) / 256, BATCH * NHEADS), 256>>>(Sb, kv_out);
    attn_out_kernel<<<dim3(NCHUNK, BATCH * NHEADS), 256>>>(Qb, Kb, Vb, Sb, g, Yb);

    // Output projection -> first output
    sgemm_nt<<<dim3(NTOK / 128, DMODEL / 128), 256>>>(Yb, Wo, out, NTOK, DMODEL, DMODEL);
}

// round 3
// speedup vs baseline: 3.0700x; 1.7386x over previous
#include <cuda_runtime.h>
#include <cuda_bf16.h>
#include <math.h>
#include <stdint.h>

// Problem constants (fixed shapes from setup_inputs)
#define BATCH 4
#define SEQ   2048
#define DMODEL 1024
#define NHEADS 16
#define FDIM  16
#define HDIM  64
#define NTOK  (BATCH*SEQ)          // 8192
#define QKDIM (NHEADS*FDIM)        // 256
#define VDIM  (NHEADS*HDIM)        // 1024
#define FEAT  273                  // 1 + 16 + 256
#define NCHUNK 16                  // 2048 / 128
#define CHUNK 128
#define KV_ELEMS (BATCH*NHEADS*HDIM*FEAT)   // 1,118,208
#define OUT_ELEMS (NTOK*DMODEL)             // 8,388,608
#define SDF (FEAT*HDIM)            // 17472

// Scratch (device globals; no runtime allocation)
__device__ float g_Q[NTOK*QKDIM];            // [tok, h*16+i]
__device__ float g_K[NTOK*QKDIM];
__device__ float g_V[NTOK*VDIM];             // [tok, h*64+f]
__device__ float g_Y[NTOK*VDIM];             // normed y, [tok, h*64+f]
__device__ float g_DS[64*NCHUNK*SDF];        // chunk states: [bh, chunk, d(273), f(64)]

__device__ __forceinline__ uint32_t f2tf32(float x) {
    uint32_t u;
    asm("cvt.rna.tf32.f32 %0, %1;" : "=r"(u) : "f"(x));
    return u;
}

// ---------------------------------------------------------------------------
// TF32 tensor-core GEMM: C[M,N] = A[M,K] @ B[N,K]^T (row-major, K contiguous)
// 128x128 block, BK=16, 8 warps of 64x32, mma.sync.m16n8k8 tf32, fp32 accum.
// ---------------------------------------------------------------------------
__global__ __launch_bounds__(256, 2)
void tgemm_nt(const float* __restrict__ A, const float* __restrict__ B,
              float* __restrict__ C, int M, int N, int K) {
    __shared__ uint32_t As[16][132];
    __shared__ uint32_t Bs[16][132];
    const int tid  = threadIdx.x;
    const int warp = tid >> 5, lane = tid & 31;
    const int gid  = lane >> 2, tig = lane & 3;
    const int wrow = warp >> 2, wcol = warp & 3;      // 2 x 4 warp grid
    const int bm = blockIdx.x * 128, bn = blockIdx.y * 128;

    // global loader mapping: thread t -> (row = t>>2 and row+64, kc = (t&3)*4)
    const int lr = tid >> 2;
    const int kc = (tid & 3) << 2;
    const float* Ap = A + (size_t)(bm + lr) * K + kc;
    const float* Bp = B + (size_t)(bn + lr) * K + kc;
    const size_t rowK64 = (size_t)64 * K;

    float acc[4][4][4];
#pragma unroll
    for (int mt = 0; mt < 4; mt++)
#pragma unroll
        for (int nt = 0; nt < 4; nt++)
#pragma unroll
            for (int e = 0; e < 4; e++) acc[mt][nt][e] = 0.f;

    // prologue: prefetch k0 = 0
    float4 av0 = *(const float4*)(Ap);
    float4 av1 = *(const float4*)(Ap + rowK64);
    float4 bv0 = *(const float4*)(Bp);
    float4 bv1 = *(const float4*)(Bp + rowK64);

    for (int k0 = 0; k0 < K; k0 += 16) {
        __syncthreads();
        As[kc + 0][lr] = f2tf32(av0.x); As[kc + 1][lr] = f2tf32(av0.y);
        As[kc + 2][lr] = f2tf32(av0.z); As[kc + 3][lr] = f2tf32(av0.w);
        As[kc + 0][lr + 64] = f2tf32(av1.x); As[kc + 1][lr + 64] = f2tf32(av1.y);
        As[kc + 2][lr + 64] = f2tf32(av1.z); As[kc + 3][lr + 64] = f2tf32(av1.w);
        Bs[kc + 0][lr] = f2tf32(bv0.x); Bs[kc + 1][lr] = f2tf32(bv0.y);
        Bs[kc + 2][lr] = f2tf32(bv0.z); Bs[kc + 3][lr] = f2tf32(bv0.w);
        Bs[kc + 0][lr + 64] = f2tf32(bv1.x); Bs[kc + 1][lr + 64] = f2tf32(bv1.y);
        Bs[kc + 2][lr + 64] = f2tf32(bv1.z); Bs[kc + 3][lr + 64] = f2tf32(bv1.w);
        __syncthreads();

        // prefetch next tile while computing this one
        if (k0 + 16 < K) {
            av0 = *(const float4*)(Ap + k0 + 16);
            av1 = *(const float4*)(Ap + k0 + 16 + rowK64);
            bv0 = *(const float4*)(Bp + k0 + 16);
            bv1 = *(const float4*)(Bp + k0 + 16 + rowK64);
        }

#pragma unroll
        for (int ks = 0; ks < 2; ks++) {
            const int kk = ks * 8;
            uint32_t af[4][4], bf[4][2];
#pragma unroll
            for (int mt = 0; mt < 4; mt++) {
                const int m = wrow * 64 + mt * 16 + gid;
                af[mt][0] = As[kk + tig][m];
                af[mt][1] = As[kk + tig][m + 8];
                af[mt][2] = As[kk + tig + 4][m];
                af[mt][3] = As[kk + tig + 4][m + 8];
            }
#pragma unroll
            for (int nt = 0; nt < 4; nt++) {
                const int n = wcol * 32 + nt * 8 + gid;
                bf[nt][0] = Bs[kk + tig][n];
                bf[nt][1] = Bs[kk + tig + 4][n];
            }
#pragma unroll
            for (int mt = 0; mt < 4; mt++)
#pragma unroll
                for (int nt = 0; nt < 4; nt++) {
                    asm volatile(
                        "mma.sync.aligned.m16n8k8.row.col.f32.tf32.tf32.f32 "
                        "{%0,%1,%2,%3}, {%4,%5,%6,%7}, {%8,%9}, {%0,%1,%2,%3};"
                        : "+f"(acc[mt][nt][0]), "+f"(acc[mt][nt][1]),
                          "+f"(acc[mt][nt][2]), "+f"(acc[mt][nt][3])
                        : "r"(af[mt][0]), "r"(af[mt][1]),
                          "r"(af[mt][2]), "r"(af[mt][3]),
                          "r"(bf[nt][0]), "r"(bf[nt][1]));
                }
        }
    }

    // epilogue
#pragma unroll
    for (int mt = 0; mt < 4; mt++) {
        const int r0 = bm + wrow * 64 + mt * 16 + gid;
#pragma unroll
        for (int nt = 0; nt < 4; nt++) {
            const int cc = bn + wcol * 32 + nt * 8 + tig * 2;
            *(float2*)&C[(size_t)r0 * N + cc] =
                make_float2(acc[mt][nt][0], acc[mt][nt][1]);
            *(float2*)&C[(size_t)(r0 + 8) * N + cc] =
                make_float2(acc[mt][nt][2], acc[mt][nt][3]);
        }
    }
}

// ---------------------------------------------------------------------------
// Kernel A: per-chunk state increment  DS[bh,ck,d,f] = sum_{n in chunk} kf[n,d] v[n,f]
// ---------------------------------------------------------------------------
__global__ __launch_bounds__(256, 2)
void state_kernel(const float* __restrict__ Km, const float* __restrict__ V,
                  float* __restrict__ DS) {
    __shared__ float ks[32][16];
    __shared__ float vs[32][64];
    const int ck = blockIdx.x;
    const int bh = blockIdx.y;
    const int b = bh >> 4, h = bh & 15;
    const int tid = threadIdx.x;
    const int i = tid >> 4;
    const int f0 = (tid & 15) << 2;
    const int tokb = b * SEQ + ck * CHUNK;

    float m2[16][4];
#pragma unroll
    for (int j = 0; j < 16; j++)
#pragma unroll
        for (int ff = 0; ff < 4; ff++) m2[j][ff] = 0.f;
    float m1[4] = {0.f, 0.f, 0.f, 0.f};
    float s0[4] = {0.f, 0.f, 0.f, 0.f};

    for (int nb = 0; nb < CHUNK; nb += 32) {
        __syncthreads();
        for (int t = tid; t < 128; t += 256) {
            int r = t >> 2, c4 = (t & 3) << 2;
            *(float4*)&ks[r][c4] =
                *(const float4*)&Km[(size_t)(tokb + nb + r) * QKDIM + h * FDIM + c4];
        }
        for (int t = tid; t < 512; t += 256) {
            int r = t >> 4, c4 = (t & 15) << 2;
            *(float4*)&vs[r][c4] =
                *(const float4*)&V[(size_t)(tokb + nb + r) * VDIM + h * HDIM + c4];
        }
        __syncthreads();
#pragma unroll 4
        for (int r = 0; r < 32; r++) {
            const float ki = ks[r][i];
            const float4 v4 = *(const float4*)&vs[r][f0];
            m1[0] = fmaf(ki, v4.x, m1[0]);
            m1[1] = fmaf(ki, v4.y, m1[1]);
            m1[2] = fmaf(ki, v4.z, m1[2]);
            m1[3] = fmaf(ki, v4.w, m1[3]);
            if (i == 0) {
                s0[0] += v4.x; s0[1] += v4.y; s0[2] += v4.z; s0[3] += v4.w;
            }
#pragma unroll
            for (int j = 0; j < 16; j++) {
                const float kk = ki * ks[r][j];
                m2[j][0] = fmaf(kk, v4.x, m2[j][0]);
                m2[j][1] = fmaf(kk, v4.y, m2[j][1]);
                m2[j][2] = fmaf(kk, v4.z, m2[j][2]);
                m2[j][3] = fmaf(kk, v4.w, m2[j][3]);
            }
        }
    }

    float* base = DS + (size_t)(bh * NCHUNK + ck) * SDF;
    const float c2 = 0.17677669529663687f;   // 1/(4*sqrt(2))
#pragma unroll
    for (int ff = 0; ff < 4; ff++) {
        const int f = f0 + ff;
#pragma unroll
        for (int j = 0; j < 16; j++)
            base[(17 + i * 16 + j) * HDIM + f] = m2[j][ff] * c2;
        base[(1 + i) * HDIM + f] = m1[ff] * 0.5f;
        if (i == 0) base[f] = s0[ff];
    }
}

// ---------------------------------------------------------------------------
// Kernel B: in-place exclusive scan over chunk states; inclusive total -> kv_state
// ---------------------------------------------------------------------------
__global__ void scan_kernel(float* __restrict__ DS, float* __restrict__ kv_out) {
    const int bh = blockIdx.y;
    const int e = blockIdx.x * 256 + threadIdx.x;
    if (e >= SDF) return;
    size_t base = (size_t)bh * NCHUNK * SDF + e;
    float run = 0.f;
#pragma unroll
    for (int c = 0; c < NCHUNK; c++) {
        float v = DS[base + (size_t)c * SDF];
        DS[base + (size_t)c * SDF] = run;
        run += v;
    }
    if (kv_out) {
        const int d = e >> 6, f = e & 63;
        kv_out[(size_t)bh * (HDIM * FEAT) + f * FEAT + d] = run;
    }
}

// ---------------------------------------------------------------------------
// Kernel C: y = qf . S_prev  +  intra-chunk causal, fused RMSNorm + g.
// ---------------------------------------------------------------------------
__global__ __launch_bounds__(256, 2)
void attn_out_kernel(const float* __restrict__ Q, const float* __restrict__ Km,
                     const float* __restrict__ V, const float* __restrict__ Sprev,
                     const float* __restrict__ g, float* __restrict__ Y) {
    __shared__ float Qs[128][16];   // q * sqrt(c2)
    __shared__ float Kc[128][16];   // raw k
    __shared__ float Vc[128][64];
    __shared__ float Ss[17][64];
    __shared__ float gs[64];
    const int ck = blockIdx.x;
    const int bh = blockIdx.y;
    const int b = bh >> 4, h = bh & 15;
    const int tid = threadIdx.x;
    const int fg = tid & 7, tg = tid >> 3;
    const int f0 = fg * 8;
    const int t0 = tg * 4;
    const int tok0 = b * SEQ + ck * CHUNK;
    const float SC  = 0.4204482076268573f;    // sqrt(1/(4*sqrt2))
    const float LIN = 1.1892071150027210f;    // (1/2)/SC
    const float DOT = 2.3784142300054421f;    // 1/SC

    for (int t = tid; t < 512; t += 256) {
        int r = t >> 2, c4 = (t & 3) << 2;
        float4 qv = *(const float4*)&Q[(size_t)(tok0 + r) * QKDIM + h * FDIM + c4];
        Qs[r][c4 + 0] = qv.x * SC; Qs[r][c4 + 1] = qv.y * SC;
        Qs[r][c4 + 2] = qv.z * SC; Qs[r][c4 + 3] = qv.w * SC;
        *(float4*)&Kc[r][c4] =
            *(const float4*)&Km[(size_t)(tok0 + r) * QKDIM + h * FDIM + c4];
    }
    for (int t = tid; t < 2048; t += 256) {
        int r = t >> 4, c4 = (t & 15) << 2;
        *(float4*)&Vc[r][c4] =
            *(const float4*)&V[(size_t)(tok0 + r) * VDIM + h * HDIM + c4];
    }
    if (tid < 64) gs[tid] = g[tid];
    const float* Sp = Sprev + (size_t)(bh * NCHUNK + ck) * SDF;
    for (int t = tid; t < 272; t += 256) {
        int r = t >> 4, c4 = (t & 15) << 2;
        *(float4*)&Ss[r][c4] = *(const float4*)&Sp[r * HDIM + c4];
    }
    __syncthreads();

    float acc[4][8];

    // ----- inter-chunk: const + linear features -----
    {
        float sv[8];
        *(float4*)&sv[0] = *(const float4*)&Ss[0][f0];
        *(float4*)&sv[4] = *(const float4*)&Ss[0][f0 + 4];
#pragma unroll
        for (int t = 0; t < 4; t++)
#pragma unroll
            for (int f = 0; f < 8; f++) acc[t][f] = sv[f];
#pragma unroll
        for (int j = 0; j < 16; j++) {
            *(float4*)&sv[0] = *(const float4*)&Ss[1 + j][f0];
            *(float4*)&sv[4] = *(const float4*)&Ss[1 + j][f0 + 4];
#pragma unroll
            for (int t = 0; t < 4; t++) {
                const float m = Qs[t0 + t][j] * LIN;
#pragma unroll
                for (int f = 0; f < 8; f++) acc[t][f] = fmaf(m, sv[f], acc[t][f]);
            }
        }
    }

    // ----- inter-chunk: quadratic features -----
    for (int i = 0; i < 16; i++) {
        __syncthreads();
        {
            int r = tid >> 4, c4 = (tid & 15) << 2;
            *(float4*)&Ss[r][c4] =
                *(const float4*)&Sp[(17 + i * 16 + r) * HDIM + c4];
        }
        __syncthreads();
        float qi[4];
#pragma unroll
        for (int t = 0; t < 4; t++) qi[t] = Qs[t0 + t][i];
#pragma unroll
        for (int j = 0; j < 16; j++) {
            float sv[8];
            *(float4*)&sv[0] = *(const float4*)&Ss[j][f0];
            *(float4*)&sv[4] = *(const float4*)&Ss[j][f0 + 4];
#pragma unroll
            for (int t = 0; t < 4; t++) {
                const float m = qi[t] * Qs[t0 + t][j];
#pragma unroll
                for (int f = 0; f < 8; f++) acc[t][f] = fmaf(m, sv[f], acc[t][f]);
            }
        }
    }

    // ----- intra-chunk causal: A = 1 + s/4 + s^2/32 -----
    float qr[4][16];
#pragma unroll
    for (int t = 0; t < 4; t++)
#pragma unroll
        for (int i = 0; i < 16; i++) qr[t][i] = Qs[t0 + t][i];

    const int mEnd = ((tid >> 5) + 1) * 16;
    for (int m = 0; m < mEnd; m++) {
        float s[4] = {0.f, 0.f, 0.f, 0.f};
#pragma unroll
        for (int i = 0; i < 16; i++) {
            const float ki = Kc[m][i];
            s[0] = fmaf(qr[0][i], ki, s[0]);
            s[1] = fmaf(qr[1][i], ki, s[1]);
            s[2] = fmaf(qr[2][i], ki, s[2]);
            s[3] = fmaf(qr[3][i], ki, s[3]);
        }
        float a[4];
#pragma unroll
        for (int t = 0; t < 4; t++) {
            const float sd = s[t] * DOT;
            float av = fmaf(sd, 0.25f, 1.0f);
            av = fmaf(sd * sd, 0.03125f, av);
            a[t] = (m <= t0 + t) ? av : 0.f;
        }
        float v[8];
        *(float4*)&v[0] = *(const float4*)&Vc[m][f0];
        *(float4*)&v[4] = *(const float4*)&Vc[m][f0 + 4];
#pragma unroll
        for (int t = 0; t < 4; t++)
#pragma unroll
            for (int f = 0; f < 8; f++)
                acc[t][f] = fmaf(a[t], v[f], acc[t][f]);
    }

    // ----- RMSNorm + gate + store -----
#pragma unroll
    for (int t = 0; t < 4; t++) {
        float ss = 0.f;
#pragma unroll
        for (int f = 0; f < 8; f++) ss = fmaf(acc[t][f], acc[t][f], ss);
        ss += __shfl_xor_sync(0xffffffffu, ss, 1);
        ss += __shfl_xor_sync(0xffffffffu, ss, 2);
        ss += __shfl_xor_sync(0xffffffffu, ss, 4);
        const float rms = rsqrtf(ss * (1.0f / 64.0f) + 1e-5f);
        float* yp = Y + (size_t)(tok0 + t0 + t) * VDIM + h * HDIM + f0;
        float4 o0, o1;
        o0.x = acc[t][0] * rms * gs[f0 + 0];
        o0.y = acc[t][1] * rms * gs[f0 + 1];
        o0.z = acc[t][2] * rms * gs[f0 + 2];
        o0.w = acc[t][3] * rms * gs[f0 + 3];
        o1.x = acc[t][4] * rms * gs[f0 + 4];
        o1.y = acc[t][5] * rms * gs[f0 + 5];
        o1.z = acc[t][6] * rms * gs[f0 + 6];
        o1.w = acc[t][7] * rms * gs[f0 + 7];
        *(float4*)&yp[0] = o0;
        *(float4*)&yp[4] = o1;
    }
}

// ---------------------------------------------------------------------------
extern "C" void kernel_launch(void* const* d_in, const int* in_sizes, int n_in,
                              void* d_out, int out_size) {
    const float* X  = (const float*)d_in[0];   // [4,2048,1024]
    const float* Wq = (const float*)d_in[1];   // [256,1024]
    const float* Wk = (const float*)d_in[2];   // [256,1024]
    const float* Wv = (const float*)d_in[3];   // [1024,1024]
    const float* Wo = (const float*)d_in[4];   // [1024,1024]
    const float* g  = (const float*)d_in[5];   // [64]
    float* out = (float*)d_out;

    float *Qb, *Kb, *Vb, *Yb, *Sb;
    cudaGetSymbolAddress((void**)&Qb, g_Q);
    cudaGetSymbolAddress((void**)&Kb, g_K);
    cudaGetSymbolAddress((void**)&Vb, g_V);
    cudaGetSymbolAddress((void**)&Yb, g_Y);
    cudaGetSymbolAddress((void**)&Sb, g_DS);

    // Projections (tf32 tensor cores)
    tgemm_nt<<<dim3(NTOK / 128, QKDIM / 128), 256>>>(X, Wq, Qb, NTOK, QKDIM, DMODEL);
    tgemm_nt<<<dim3(NTOK / 128, QKDIM / 128), 256>>>(X, Wk, Kb, NTOK, QKDIM, DMODEL);
    tgemm_nt<<<dim3(NTOK / 128, VDIM / 128),  256>>>(X, Wv, Vb, NTOK, VDIM,  DMODEL);

    // Chunked linear attention
    float* kv_out = (out_size >= OUT_ELEMS + KV_ELEMS) ? (out + OUT_ELEMS) : nullptr;
    state_kernel<<<dim3(NCHUNK, BATCH * NHEADS), 256>>>(Kb, Vb, Sb);
    scan_kernel<<<dim3((SDF + 255) / 256, BATCH * NHEADS), 256>>>(Sb, kv_out);
    attn_out_kernel<<<dim3(NCHUNK, BATCH * NHEADS), 256>>>(Qb, Kb, Vb, Sb, g, Yb);

    // Output projection -> first output (tf32 tensor cores)
    tgemm_nt<<<dim3(NTOK / 128, DMODEL / 128), 256>>>(Yb, Wo, out, NTOK, DMODEL, DMODEL);
}

// round 4
// speedup vs baseline: 3.4593x; 1.1268x over previous
#include <cuda_runtime.h>
#include <cuda_bf16.h>
#include <math.h>
#include <stdint.h>

// Problem constants (fixed shapes from setup_inputs)
#define BATCH 4
#define SEQ   2048
#define DMODEL 1024
#define NHEADS 16
#define FDIM  16
#define HDIM  64
#define NTOK  (BATCH*SEQ)          // 8192
#define QKDIM (NHEADS*FDIM)        // 256
#define VDIM  (NHEADS*HDIM)        // 1024
#define FEAT  273                  // 1 + 16 + 256
#define NCHUNK 16                  // 2048 / 128
#define CHUNK 128
#define KV_ELEMS (BATCH*NHEADS*HDIM*FEAT)   // 1,118,208
#define OUT_ELEMS (NTOK*DMODEL)             // 8,388,608
#define SDF (FEAT*HDIM)            // 17472

// Scratch (device globals; no runtime allocation)
__device__ float g_Q[NTOK*QKDIM];            // [tok, h*16+i]
__device__ float g_K[NTOK*QKDIM];
__device__ float g_V[NTOK*VDIM];             // [tok, h*64+f]
__device__ float g_Y[NTOK*VDIM];             // normed y, [tok, h*64+f]
__device__ float g_DS[64*NCHUNK*SDF];        // chunk states: [bh, chunk, d(273), f(64)]

__device__ __forceinline__ uint32_t f2tf32(float x) {
    uint32_t u;
    asm("cvt.rna.tf32.f32 %0, %1;" : "=r"(u) : "f"(x));
    return u;
}

// ---------------------------------------------------------------------------
// TF32 tensor-core GEMM: C[M,N] = A[M,K] @ B[N,K]^T (row-major, K contiguous)
// 128x128 block, 4 warps of 64x64, BK=16, 2-stage double-buffered smem,
// mma.sync.m16n8k8 tf32, fp32 accum. [row][k] smem layout, pad 20.
// ---------------------------------------------------------------------------
#define GPAD 20
__global__ __launch_bounds__(128)
void tgemm_nt(const float* __restrict__ A, const float* __restrict__ B,
              float* __restrict__ C, int M, int N, int K) {
    __shared__ uint32_t As[2][128][GPAD];
    __shared__ uint32_t Bs[2][128][GPAD];
    const int tid  = threadIdx.x;
    const int warp = tid >> 5, lane = tid & 31;
    const int gid  = lane >> 2, tig = lane & 3;
    const int wm = (warp >> 1) * 64, wn = (warp & 1) * 64;
    const int bm = blockIdx.x * 128, bn = blockIdx.y * 128;

    // loader mapping: row = (tid>>2) + 32p, kc = (tid&3)*4
    const int lr = tid >> 2;
    const int kc = (tid & 3) << 2;
    const float* Ap = A + (size_t)(bm + lr) * K + kc;
    const float* Bp = B + (size_t)(bn + lr) * K + kc;
    const size_t row32 = (size_t)32 * K;

    float acc[4][8][4];
#pragma unroll
    for (int mt = 0; mt < 4; mt++)
#pragma unroll
        for (int nt = 0; nt < 8; nt++)
#pragma unroll
            for (int e = 0; e < 4; e++) acc[mt][nt][e] = 0.f;

    float4 ar[4], br[4];
    // prologue: load + stage k0 = 0 into stage 0
#pragma unroll
    for (int p = 0; p < 4; p++) {
        ar[p] = *(const float4*)(Ap + p * row32);
        br[p] = *(const float4*)(Bp + p * row32);
    }
#pragma unroll
    for (int p = 0; p < 4; p++) {
        uint32_t* as = &As[0][lr + p * 32][kc];
        as[0] = f2tf32(ar[p].x); as[1] = f2tf32(ar[p].y);
        as[2] = f2tf32(ar[p].z); as[3] = f2tf32(ar[p].w);
        uint32_t* bs = &Bs[0][lr + p * 32][kc];
        bs[0] = f2tf32(br[p].x); bs[1] = f2tf32(br[p].y);
        bs[2] = f2tf32(br[p].z); bs[3] = f2tf32(br[p].w);
    }
    __syncthreads();

    int cur = 0;
    for (int k0 = 0; k0 < K; k0 += 16) {
        const bool more = (k0 + 16 < K);
        if (more) {
#pragma unroll
            for (int p = 0; p < 4; p++) {
                ar[p] = *(const float4*)(Ap + k0 + 16 + p * row32);
                br[p] = *(const float4*)(Bp + k0 + 16 + p * row32);
            }
        }

#pragma unroll
        for (int ks = 0; ks < 2; ks++) {
            const int kk = ks * 8;
            uint32_t af[4][4], bf[8][2];
#pragma unroll
            for (int mt = 0; mt < 4; mt++) {
                const int m = wm + mt * 16 + gid;
                af[mt][0] = As[cur][m][kk + tig];
                af[mt][1] = As[cur][m + 8][kk + tig];
                af[mt][2] = As[cur][m][kk + tig + 4];
                af[mt][3] = As[cur][m + 8][kk + tig + 4];
            }
#pragma unroll
            for (int nt = 0; nt < 8; nt++) {
                const int n = wn + nt * 8 + gid;
                bf[nt][0] = Bs[cur][n][kk + tig];
                bf[nt][1] = Bs[cur][n][kk + tig + 4];
            }
#pragma unroll
            for (int mt = 0; mt < 4; mt++)
#pragma unroll
                for (int nt = 0; nt < 8; nt++) {
                    asm volatile(
                        "mma.sync.aligned.m16n8k8.row.col.f32.tf32.tf32.f32 "
                        "{%0,%1,%2,%3}, {%4,%5,%6,%7}, {%8,%9}, {%0,%1,%2,%3};"
                        : "+f"(acc[mt][nt][0]), "+f"(acc[mt][nt][1]),
                          "+f"(acc[mt][nt][2]), "+f"(acc[mt][nt][3])
                        : "r"(af[mt][0]), "r"(af[mt][1]),
                          "r"(af[mt][2]), "r"(af[mt][3]),
                          "r"(bf[nt][0]), "r"(bf[nt][1]));
                }
        }

        if (more) {
            const int nxt = cur ^ 1;
#pragma unroll
            for (int p = 0; p < 4; p++) {
                uint32_t* as = &As[nxt][lr + p * 32][kc];
                as[0] = f2tf32(ar[p].x); as[1] = f2tf32(ar[p].y);
                as[2] = f2tf32(ar[p].z); as[3] = f2tf32(ar[p].w);
                uint32_t* bs = &Bs[nxt][lr + p * 32][kc];
                bs[0] = f2tf32(br[p].x); bs[1] = f2tf32(br[p].y);
                bs[2] = f2tf32(br[p].z); bs[3] = f2tf32(br[p].w);
            }
            __syncthreads();
        }
        cur ^= 1;
    }

    // epilogue
#pragma unroll
    for (int mt = 0; mt < 4; mt++) {
        const int r0 = bm + wm + mt * 16 + gid;
#pragma unroll
        for (int nt = 0; nt < 8; nt++) {
            const int cc = bn + wn + nt * 8 + tig * 2;
            *(float2*)&C[(size_t)r0 * N + cc] =
                make_float2(acc[mt][nt][0], acc[mt][nt][1]);
            *(float2*)&C[(size_t)(r0 + 8) * N + cc] =
                make_float2(acc[mt][nt][2], acc[mt][nt][3]);
        }
    }
}

// ---------------------------------------------------------------------------
// Kernel A: per-chunk state increment  DS[bh,ck,d,f] = sum_{n in chunk} kf[n,d] v[n,f]
// ---------------------------------------------------------------------------
__global__ __launch_bounds__(256, 2)
void state_kernel(const float* __restrict__ Km, const float* __restrict__ V,
                  float* __restrict__ DS) {
    __shared__ float ks[32][16];
    __shared__ float vs[32][64];
    const int ck = blockIdx.x;
    const int bh = blockIdx.y;
    const int b = bh >> 4, h = bh & 15;
    const int tid = threadIdx.x;
    const int i = tid >> 4;
    const int f0 = (tid & 15) << 2;
    const int tokb = b * SEQ + ck * CHUNK;

    float m2[16][4];
#pragma unroll
    for (int j = 0; j < 16; j++)
#pragma unroll
        for (int ff = 0; ff < 4; ff++) m2[j][ff] = 0.f;
    float m1[4] = {0.f, 0.f, 0.f, 0.f};
    float s0[4] = {0.f, 0.f, 0.f, 0.f};

    for (int nb = 0; nb < CHUNK; nb += 32) {
        __syncthreads();
        for (int t = tid; t < 128; t += 256) {
            int r = t >> 2, c4 = (t & 3) << 2;
            *(float4*)&ks[r][c4] =
                *(const float4*)&Km[(size_t)(tokb + nb + r) * QKDIM + h * FDIM + c4];
        }
        for (int t = tid; t < 512; t += 256) {
            int r = t >> 4, c4 = (t & 15) << 2;
            *(float4*)&vs[r][c4] =
                *(const float4*)&V[(size_t)(tokb + nb + r) * VDIM + h * HDIM + c4];
        }
        __syncthreads();
#pragma unroll 4
        for (int r = 0; r < 32; r++) {
            const float ki = ks[r][i];
            const float4 v4 = *(const float4*)&vs[r][f0];
            m1[0] = fmaf(ki, v4.x, m1[0]);
            m1[1] = fmaf(ki, v4.y, m1[1]);
            m1[2] = fmaf(ki, v4.z, m1[2]);
            m1[3] = fmaf(ki, v4.w, m1[3]);
            if (i == 0) {
                s0[0] += v4.x; s0[1] += v4.y; s0[2] += v4.z; s0[3] += v4.w;
            }
#pragma unroll
            for (int j = 0; j < 16; j++) {
                const float kk = ki * ks[r][j];
                m2[j][0] = fmaf(kk, v4.x, m2[j][0]);
                m2[j][1] = fmaf(kk, v4.y, m2[j][1]);
                m2[j][2] = fmaf(kk, v4.z, m2[j][2]);
                m2[j][3] = fmaf(kk, v4.w, m2[j][3]);
            }
        }
    }

    float* base = DS + (size_t)(bh * NCHUNK + ck) * SDF;
    const float c2 = 0.17677669529663687f;   // 1/(4*sqrt(2))
#pragma unroll
    for (int ff = 0; ff < 4; ff++) {
        const int f = f0 + ff;
#pragma unroll
        for (int j = 0; j < 16; j++)
            base[(17 + i * 16 + j) * HDIM + f] = m2[j][ff] * c2;
        base[(1 + i) * HDIM + f] = m1[ff] * 0.5f;
        if (i == 0) base[f] = s0[ff];
    }
}

// ---------------------------------------------------------------------------
// Kernel B: in-place exclusive scan over chunk states; inclusive total -> kv_state
// ---------------------------------------------------------------------------
__global__ void scan_kernel(float* __restrict__ DS, float* __restrict__ kv_out) {
    const int bh = blockIdx.y;
    const int e = blockIdx.x * 256 + threadIdx.x;
    if (e >= SDF) return;
    size_t base = (size_t)bh * NCHUNK * SDF + e;
    float run = 0.f;
#pragma unroll
    for (int c = 0; c < NCHUNK; c++) {
        float v = DS[base + (size_t)c * SDF];
        DS[base + (size_t)c * SDF] = run;
        run += v;
    }
    if (kv_out) {
        const int d = e >> 6, f = e & 63;
        kv_out[(size_t)bh * (HDIM * FEAT) + f * FEAT + d] = run;
    }
}

// ---------------------------------------------------------------------------
// Kernel C: y = qf . S_prev  +  intra-chunk causal, fused RMSNorm + g.
// ---------------------------------------------------------------------------
__global__ __launch_bounds__(256, 2)
void attn_out_kernel(const float* __restrict__ Q, const float* __restrict__ Km,
                     const float* __restrict__ V, const float* __restrict__ Sprev,
                     const float* __restrict__ g, float* __restrict__ Y) {
    __shared__ float Qs[128][16];   // q * sqrt(c2)
    __shared__ float Kc[128][16];   // raw k
    __shared__ float Vc[128][64];
    __shared__ float Ss[17][64];
    __shared__ float gs[64];
    const int ck = blockIdx.x;
    const int bh = blockIdx.y;
    const int b = bh >> 4, h = bh & 15;
    const int tid = threadIdx.x;
    const int fg = tid & 7, tg = tid >> 3;
    const int f0 = fg * 8;
    const int t0 = tg * 4;
    const int tok0 = b * SEQ + ck * CHUNK;
    const float SC  = 0.4204482076268573f;    // sqrt(1/(4*sqrt2))
    const float LIN = 1.1892071150027210f;    // (1/2)/SC
    const float DOT = 2.3784142300054421f;    // 1/SC

    for (int t = tid; t < 512; t += 256) {
        int r = t >> 2, c4 = (t & 3) << 2;
        float4 qv = *(const float4*)&Q[(size_t)(tok0 + r) * QKDIM + h * FDIM + c4];
        Qs[r][c4 + 0] = qv.x * SC; Qs[r][c4 + 1] = qv.y * SC;
        Qs[r][c4 + 2] = qv.z * SC; Qs[r][c4 + 3] = qv.w * SC;
        *(float4*)&Kc[r][c4] =
            *(const float4*)&Km[(size_t)(tok0 + r) * QKDIM + h * FDIM + c4];
    }
    for (int t = tid; t < 2048; t += 256) {
        int r = t >> 4, c4 = (t & 15) << 2;
        *(float4*)&Vc[r][c4] =
            *(const float4*)&V[(size_t)(tok0 + r) * VDIM + h * HDIM + c4];
    }
    if (tid < 64) gs[tid] = g[tid];
    const float* Sp = Sprev + (size_t)(bh * NCHUNK + ck) * SDF;
    for (int t = tid; t < 272; t += 256) {
        int r = t >> 4, c4 = (t & 15) << 2;
        *(float4*)&Ss[r][c4] = *(const float4*)&Sp[r * HDIM + c4];
    }
    __syncthreads();

    float acc[4][8];

    // ----- inter-chunk: const + linear features -----
    {
        float sv[8];
        *(float4*)&sv[0] = *(const float4*)&Ss[0][f0];
        *(float4*)&sv[4] = *(const float4*)&Ss[0][f0 + 4];
#pragma unroll
        for (int t = 0; t < 4; t++)
#pragma unroll
            for (int f = 0; f < 8; f++) acc[t][f] = sv[f];
#pragma unroll
        for (int j = 0; j < 16; j++) {
            *(float4*)&sv[0] = *(const float4*)&Ss[1 + j][f0];
            *(float4*)&sv[4] = *(const float4*)&Ss[1 + j][f0 + 4];
#pragma unroll
            for (int t = 0; t < 4; t++) {
                const float m = Qs[t0 + t][j] * LIN;
#pragma unroll
                for (int f = 0; f < 8; f++) acc[t][f] = fmaf(m, sv[f], acc[t][f]);
            }
        }
    }

    // ----- inter-chunk: quadratic features -----
    for (int i = 0; i < 16; i++) {
        __syncthreads();
        {
            int r = tid >> 4, c4 = (tid & 15) << 2;
            *(float4*)&Ss[r][c4] =
                *(const float4*)&Sp[(17 + i * 16 + r) * HDIM + c4];
        }
        __syncthreads();
        float qi[4];
#pragma unroll
        for (int t = 0; t < 4; t++) qi[t] = Qs[t0 + t][i];
#pragma unroll
        for (int j = 0; j < 16; j++) {
            float sv[8];
            *(float4*)&sv[0] = *(const float4*)&Ss[j][f0];
            *(float4*)&sv[4] = *(const float4*)&Ss[j][f0 + 4];
#pragma unroll
            for (int t = 0; t < 4; t++) {
                const float m = qi[t] * Qs[t0 + t][j];
#pragma unroll
                for (int f = 0; f < 8; f++) acc[t][f] = fmaf(m, sv[f], acc[t][f]);
            }
        }
    }

    // ----- intra-chunk causal: A = 1 + s/4 + s^2/32 -----
    float qr[4][16];
#pragma unroll
    for (int t = 0; t < 4; t++)
#pragma unroll
        for (int i = 0; i < 16; i++) qr[t][i] = Qs[t0 + t][i];

    const int mEnd = ((tid >> 5) + 1) * 16;
    for (int m = 0; m < mEnd; m++) {
        float s[4] = {0.f, 0.f, 0.f, 0.f};
#pragma unroll
        for (int i = 0; i < 16; i++) {
            const float ki = Kc[m][i];
            s[0] = fmaf(qr[0][i], ki, s[0]);
            s[1] = fmaf(qr[1][i], ki, s[1]);
            s[2] = fmaf(qr[2][i], ki, s[2]);
            s[3] = fmaf(qr[3][i], ki, s[3]);
        }
        float a[4];
#pragma unroll
        for (int t = 0; t < 4; t++) {
            const float sd = s[t] * DOT;
            float av = fmaf(sd, 0.25f, 1.0f);
            av = fmaf(sd * sd, 0.03125f, av);
            a[t] = (m <= t0 + t) ? av : 0.f;
        }
        float v[8];
        *(float4*)&v[0] = *(const float4*)&Vc[m][f0];
        *(float4*)&v[4] = *(const float4*)&Vc[m][f0 + 4];
#pragma unroll
        for (int t = 0; t < 4; t++)
#pragma unroll
            for (int f = 0; f < 8; f++)
                acc[t][f] = fmaf(a[t], v[f], acc[t][f]);
    }

    // ----- RMSNorm + gate + store -----
#pragma unroll
    for (int t = 0; t < 4; t++) {
        float ss = 0.f;
#pragma unroll
        for (int f = 0; f < 8; f++) ss = fmaf(acc[t][f], acc[t][f], ss);
        ss += __shfl_xor_sync(0xffffffffu, ss, 1);
        ss += __shfl_xor_sync(0xffffffffu, ss, 2);
        ss += __shfl_xor_sync(0xffffffffu, ss, 4);
        const float rms = rsqrtf(ss * (1.0f / 64.0f) + 1e-5f);
        float* yp = Y + (size_t)(tok0 + t0 + t) * VDIM + h * HDIM + f0;
        float4 o0, o1;
        o0.x = acc[t][0] * rms * gs[f0 + 0];
        o0.y = acc[t][1] * rms * gs[f0 + 1];
        o0.z = acc[t][2] * rms * gs[f0 + 2];
        o0.w = acc[t][3] * rms * gs[f0 + 3];
        o1.x = acc[t][4] * rms * gs[f0 + 4];
        o1.y = acc[t][5] * rms * gs[f0 + 5];
        o1.z = acc[t][6] * rms * gs[f0 + 6];
        o1.w = acc[t][7] * rms * gs[f0 + 7];
        *(float4*)&yp[0] = o0;
        *(float4*)&yp[4] = o1;
    }
}

// ---------------------------------------------------------------------------
extern "C" void kernel_launch(void* const* d_in, const int* in_sizes, int n_in,
                              void* d_out, int out_size) {
    const float* X  = (const float*)d_in[0];   // [4,2048,1024]
    const float* Wq = (const float*)d_in[1];   // [256,1024]
    const float* Wk = (const float*)d_in[2];   // [256,1024]
    const float* Wv = (const float*)d_in[3];   // [1024,1024]
    const float* Wo = (const float*)d_in[4];   // [1024,1024]
    const float* g  = (const float*)d_in[5];   // [64]
    float* out = (float*)d_out;

    float *Qb, *Kb, *Vb, *Yb, *Sb;
    cudaGetSymbolAddress((void**)&Qb, g_Q);
    cudaGetSymbolAddress((void**)&Kb, g_K);
    cudaGetSymbolAddress((void**)&Vb, g_V);
    cudaGetSymbolAddress((void**)&Yb, g_Y);
    cudaGetSymbolAddress((void**)&Sb, g_DS);

    // Projections (tf32 tensor cores, double-buffered)
    tgemm_nt<<<dim3(NTOK / 128, QKDIM / 128), 128>>>(X, Wq, Qb, NTOK, QKDIM, DMODEL);
    tgemm_nt<<<dim3(NTOK / 128, QKDIM / 128), 128>>>(X, Wk, Kb, NTOK, QKDIM, DMODEL);
    tgemm_nt<<<dim3(NTOK / 128, VDIM / 128),  128>>>(X, Wv, Vb, NTOK, VDIM,  DMODEL);

    // Chunked linear attention
    float* kv_out = (out_size >= OUT_ELEMS + KV_ELEMS) ? (out + OUT_ELEMS) : nullptr;
    state_kernel<<<dim3(NCHUNK, BATCH * NHEADS), 256>>>(Kb, Vb, Sb);
    scan_kernel<<<dim3((SDF + 255) / 256, BATCH * NHEADS), 256>>>(Sb, kv_out);
    attn_out_kernel<<<dim3(NCHUNK, BATCH * NHEADS), 256>>>(Qb, Kb, Vb, Sb, g, Yb);

    // Output projection -> first output (tf32 tensor cores)
    tgemm_nt<<<dim3(NTOK / 128, DMODEL / 128), 128>>>(Yb, Wo, out, NTOK, DMODEL, DMODEL);
}